// round 5
// baseline (speedup 1.0000x reference)
#include <cuda_runtime.h>
#include <cuda_bf16.h>
#include <math_constants.h>

#define N_NODES 100000
#define N_EDGES 1600000
#define IN_CH   128
#define OUT_CH  64
#define NEG_SLOPE 0.2f
#define EPS_F 1e-10f

// ---------------- scratch (no allocations allowed) ----------------
__device__ float g_h[(size_t)N_NODES * OUT_CH];   // 25.6 MB
__device__ float g_el[N_NODES];
__device__ float g_er[N_NODES];
__device__ float g_max[N_NODES];
__device__ float g_sum[N_NODES];

// ---------------- helpers ----------------
__device__ __forceinline__ void atomicMaxFloat(float* addr, float value) {
    if (value >= 0.0f) {
        atomicMax(reinterpret_cast<int*>(addr), __float_as_int(value));
    } else {
        atomicMin(reinterpret_cast<unsigned int*>(addr), __float_as_uint(value));
    }
}

__device__ __forceinline__ float leaky(float x) {
    return x > 0.0f ? x : NEG_SLOPE * x;
}

// ---------------- K0: init out with bias, init max/sum ----------------
__global__ void init_kernel(float* __restrict__ out, const float* __restrict__ bias) {
    int i = blockIdx.x * blockDim.x + threadIdx.x;
    int total = N_NODES * OUT_CH;
    if (i < total) {
        out[i] = bias[i & (OUT_CH - 1)];
    }
    if (i < N_NODES) {
        g_max[i] = -CUDART_INF_F;
        g_sum[i] = 0.0f;
    }
}

// ---------------- K1: h = x @ W^T ----------------
// block: 256 threads, 16 rows per block; exactly 6250 blocks.
__global__ void gemm_kernel(const float* __restrict__ x, const float* __restrict__ W) {
    __shared__ float sw[IN_CH][OUT_CH + 1];  // W transposed: sw[k][oc]
    __shared__ float sx[16][IN_CH];

    int tid = threadIdx.x;
    // load W transposed (W is [OUT_CH][IN_CH] row-major)
    for (int i = tid; i < OUT_CH * IN_CH; i += 256) {
        int oc = i / IN_CH;
        int k  = i - oc * IN_CH;
        sw[k][oc] = W[i];
    }
    int rb = blockIdx.x * 16;
    // load x tile: 16 rows x 128
    for (int i = tid; i < 16 * IN_CH; i += 256) {
        int r = i / IN_CH;
        int k = i - r * IN_CH;
        int row = rb + r;
        sx[r][k] = (row < N_NODES) ? x[(size_t)row * IN_CH + k] : 0.0f;
    }
    __syncthreads();

    int oc = tid & 63;        // 0..63
    int rg = tid >> 6;        // 0..3 -> rows rg*4 .. rg*4+3
    float acc0 = 0.f, acc1 = 0.f, acc2 = 0.f, acc3 = 0.f;
    int r0 = rg * 4;
#pragma unroll
    for (int k = 0; k < IN_CH; k++) {
        float w = sw[k][oc];
        acc0 = fmaf(sx[r0 + 0][k], w, acc0);
        acc1 = fmaf(sx[r0 + 1][k], w, acc1);
        acc2 = fmaf(sx[r0 + 2][k], w, acc2);
        acc3 = fmaf(sx[r0 + 3][k], w, acc3);
    }
    int row = rb + r0;
    if (row + 0 < N_NODES) g_h[(size_t)(row + 0) * OUT_CH + oc] = acc0;
    if (row + 1 < N_NODES) g_h[(size_t)(row + 1) * OUT_CH + oc] = acc1;
    if (row + 2 < N_NODES) g_h[(size_t)(row + 2) * OUT_CH + oc] = acc2;
    if (row + 3 < N_NODES) g_h[(size_t)(row + 3) * OUT_CH + oc] = acc3;
}

// ---------------- K2: e_l = h @ a_l, e_r = h @ a_r (warp per node) ----------------
__global__ void elr_kernel(const float* __restrict__ a_l, const float* __restrict__ a_r) {
    int gtid = blockIdx.x * blockDim.x + threadIdx.x;
    int node = gtid >> 5;
    int lane = gtid & 31;
    if (node >= N_NODES) return;
    float h0 = g_h[(size_t)node * OUT_CH + lane];
    float h1 = g_h[(size_t)node * OUT_CH + 32 + lane];
    float pl = h0 * a_l[lane] + h1 * a_l[32 + lane];
    float pr = h0 * a_r[lane] + h1 * a_r[32 + lane];
#pragma unroll
    for (int off = 16; off > 0; off >>= 1) {
        pl += __shfl_down_sync(0xFFFFFFFFu, pl, off);
        pr += __shfl_down_sync(0xFFFFFFFFu, pr, off);
    }
    if (lane == 0) {
        g_el[node] = pl;
        g_er[node] = pr;
    }
}

// ---------------- K3: segment max over dst (edge_index is int32!) ----------------
__global__ void edge_max_kernel(const int* __restrict__ ei) {
    int e = blockIdx.x * blockDim.x + threadIdx.x;
    if (e >= N_EDGES) return;
    int src = ei[e];
    int dst = ei[N_EDGES + e];
    float a = leaky(g_el[dst] + g_er[src]);
    atomicMaxFloat(&g_max[dst], a);
}

// ---------------- K4: segment sum of exp ----------------
__global__ void edge_sum_kernel(const int* __restrict__ ei) {
    int e = blockIdx.x * blockDim.x + threadIdx.x;
    if (e >= N_EDGES) return;
    int src = ei[e];
    int dst = ei[N_EDGES + e];
    float a = leaky(g_el[dst] + g_er[src]);
    float w = __expf(a - g_max[dst]);
    atomicAdd(&g_sum[dst], w);
}

// ---------------- K5: weighted message scatter (warp per edge, scalar atomics) ----------------
__global__ void msg_kernel(const int* __restrict__ ei, float* __restrict__ out) {
    int gtid = blockIdx.x * blockDim.x + threadIdx.x;
    int e = gtid >> 5;
    int lane = gtid & 31;
    if (e >= N_EDGES) return;
    int src = ei[e];
    int dst = ei[N_EDGES + e];
    float a = leaky(g_el[dst] + g_er[src]);
    float w = __expf(a - g_max[dst]) / (g_sum[dst] + EPS_F);
    const float* hp = g_h + (size_t)src * OUT_CH;
    float v0 = hp[lane] * w;
    float v1 = hp[lane + 32] * w;
    float* op = out + (size_t)dst * OUT_CH;
    atomicAdd(op + lane, v0);
    atomicAdd(op + lane + 32, v1);
}

// ---------------- launch ----------------
extern "C" void kernel_launch(void* const* d_in, const int* in_sizes, int n_in,
                              void* d_out, int out_size) {
    const float* x    = (const float*)d_in[0];
    const int*   ei   = (const int*)d_in[1];     // int32 (JAX x64 disabled)
    const float* W    = (const float*)d_in[2];
    const float* a_l  = (const float*)d_in[3];
    const float* a_r  = (const float*)d_in[4];
    const float* bias = (const float*)d_in[5];
    float* out = (float*)d_out;

    (void)in_sizes; (void)n_in; (void)out_size;

    // K0: init
    {
        int total = N_NODES * OUT_CH;
        init_kernel<<<(total + 255) / 256, 256>>>(out, bias);
    }
    // K1: GEMM h = x W^T
    gemm_kernel<<<(N_NODES + 15) / 16, 256>>>(x, W);
    // K2: e_l / e_r
    {
        int blocks = (N_NODES * 32 + 255) / 256;
        elr_kernel<<<blocks, 256>>>(a_l, a_r);
    }
    // K3: segment max
    edge_max_kernel<<<(N_EDGES + 255) / 256, 256>>>(ei);
    // K4: segment sum of exp
    edge_sum_kernel<<<(N_EDGES + 255) / 256, 256>>>(ei);
    // K5: messages
    {
        long long threads = (long long)N_EDGES * 32;
        int blocks = (int)((threads + 255) / 256);
        msg_kernel<<<blocks, 256>>>(ei, out);
    }
}

// round 6
// speedup vs baseline: 1.6412x; 1.6412x over previous
#include <cuda_runtime.h>
#include <cuda_bf16.h>
#include <math_constants.h>

#define N_NODES 100000
#define N_EDGES 1600000
#define IN_CH   128
#define OUT_CH  64
#define NEG_SLOPE 0.2f
#define EPS_F 1e-10f

#define SCAN_BS 1024
#define NUM_SCAN_BLOCKS ((N_NODES + SCAN_BS - 1) / SCAN_BS)   // 98

// ---------------- scratch (no allocations allowed) ----------------
__device__ float g_h[(size_t)N_NODES * OUT_CH];   // 25.6 MB
__device__ float g_el[N_NODES];
__device__ float g_er[N_NODES];
__device__ int   g_deg[N_NODES];
__device__ int   g_fill[N_NODES];
__device__ int   g_rowptr[N_NODES + 1];
__device__ int   g_bsum[NUM_SCAN_BLOCKS];
__device__ int   g_src_sorted[N_EDGES];

__device__ __forceinline__ float leaky(float v) {
    return v > 0.0f ? v : NEG_SLOPE * v;
}

// ---------------- K0: zero deg/fill ----------------
__global__ void init_kernel() {
    int i = blockIdx.x * blockDim.x + threadIdx.x;
    if (i < N_NODES) {
        g_deg[i]  = 0;
        g_fill[i] = 0;
    }
}

// ---------------- K1: h = x @ W^T ----------------
// 128 rows/block, k-chunks of 32, 128 threads, 8x8 register tile.
#define GEMM_ROWS 128
#define GEMM_KC   32
__global__ __launch_bounds__(128) void gemm_kernel(const float* __restrict__ x,
                                                   const float* __restrict__ W) {
    __shared__ float sw[GEMM_KC][OUT_CH];          // 8 KB   sw[k][oc]
    __shared__ float sx[GEMM_KC][GEMM_ROWS + 1];   // 16.5KB sx[k][row]

    int tid = threadIdx.x;
    int tx  = tid & 7;    // col group: cols tx*8 .. tx*8+7
    int ty  = tid >> 3;   // row group: rows ty*8 .. ty*8+7  (0..15)
    int row0 = blockIdx.x * GEMM_ROWS;

    float acc[8][8];
#pragma unroll
    for (int i = 0; i < 8; i++)
#pragma unroll
        for (int j = 0; j < 8; j++) acc[i][j] = 0.0f;

    for (int kc = 0; kc < IN_CH; kc += GEMM_KC) {
        // stage W chunk: W[oc][kc+k] -> sw[k][oc]
        for (int i = tid; i < GEMM_KC * OUT_CH; i += 128) {
            int oc = i >> 5;        // i / 32
            int k  = i & 31;
            sw[k][oc] = W[oc * IN_CH + kc + k];
        }
        // stage x chunk: sx[k][r] = x[row0+r][kc+k]   (coalesced reads)
        for (int i = tid; i < GEMM_ROWS * GEMM_KC; i += 128) {
            int r = i >> 5;
            int k = i & 31;
            int row = row0 + r;
            sx[k][r] = (row < N_NODES) ? x[(size_t)row * IN_CH + kc + k] : 0.0f;
        }
        __syncthreads();

#pragma unroll
        for (int k = 0; k < GEMM_KC; k++) {
            float xv[8], wv[8];
#pragma unroll
            for (int i = 0; i < 8; i++) xv[i] = sx[k][ty * 8 + i];
#pragma unroll
            for (int j = 0; j < 8; j++) wv[j] = sw[k][tx * 8 + j];
#pragma unroll
            for (int i = 0; i < 8; i++)
#pragma unroll
                for (int j = 0; j < 8; j++)
                    acc[i][j] = fmaf(xv[i], wv[j], acc[i][j]);
        }
        __syncthreads();
    }

#pragma unroll
    for (int i = 0; i < 8; i++) {
        int row = row0 + ty * 8 + i;
        if (row < N_NODES) {
            float4* dst = reinterpret_cast<float4*>(g_h + (size_t)row * OUT_CH + tx * 8);
            dst[0] = make_float4(acc[i][0], acc[i][1], acc[i][2], acc[i][3]);
            dst[1] = make_float4(acc[i][4], acc[i][5], acc[i][6], acc[i][7]);
        }
    }
}

// ---------------- K2: e_l = h @ a_l, e_r = h @ a_r (warp per node) ----------------
__global__ void elr_kernel(const float* __restrict__ a_l, const float* __restrict__ a_r) {
    int gtid = blockIdx.x * blockDim.x + threadIdx.x;
    int node = gtid >> 5;
    int lane = gtid & 31;
    if (node >= N_NODES) return;
    float h0 = g_h[(size_t)node * OUT_CH + lane];
    float h1 = g_h[(size_t)node * OUT_CH + 32 + lane];
    float pl = h0 * a_l[lane] + h1 * a_l[32 + lane];
    float pr = h0 * a_r[lane] + h1 * a_r[32 + lane];
#pragma unroll
    for (int off = 16; off > 0; off >>= 1) {
        pl += __shfl_down_sync(0xFFFFFFFFu, pl, off);
        pr += __shfl_down_sync(0xFFFFFFFFu, pr, off);
    }
    if (lane == 0) {
        g_el[node] = pl;
        g_er[node] = pr;
    }
}

// ---------------- K3: histogram of dst ----------------
__global__ void hist_kernel(const int* __restrict__ ei) {
    int e = blockIdx.x * blockDim.x + threadIdx.x;
    if (e >= N_EDGES) return;
    atomicAdd(&g_deg[ei[N_EDGES + e]], 1);
}

// ---------------- K4a: per-block inclusive scan of deg ----------------
__global__ void scan_block_kernel() {
    __shared__ int warp_sums[32];
    int i = blockIdx.x * SCAN_BS + threadIdx.x;
    int lane = threadIdx.x & 31, wid = threadIdx.x >> 5;
    int v = (i < N_NODES) ? g_deg[i] : 0;
    int s = v;
#pragma unroll
    for (int o = 1; o < 32; o <<= 1) {
        int t = __shfl_up_sync(0xFFFFFFFFu, s, o);
        if (lane >= o) s += t;
    }
    if (lane == 31) warp_sums[wid] = s;
    __syncthreads();
    if (wid == 0) {
        int ws = warp_sums[lane];
#pragma unroll
        for (int o = 1; o < 32; o <<= 1) {
            int t = __shfl_up_sync(0xFFFFFFFFu, ws, o);
            if (lane >= o) ws += t;
        }
        warp_sums[lane] = ws;
    }
    __syncthreads();
    int incl = s + (wid > 0 ? warp_sums[wid - 1] : 0);
    if (i < N_NODES) g_rowptr[i + 1] = incl;
    if (threadIdx.x == SCAN_BS - 1) g_bsum[blockIdx.x] = incl;
}

// ---------------- K4b: exclusive scan of block sums (1 block) ----------------
__global__ void scan_bsum_kernel() {
    __shared__ int sh[NUM_SCAN_BLOCKS];
    int t = threadIdx.x;
    if (t < NUM_SCAN_BLOCKS) sh[t] = g_bsum[t];
    __syncthreads();
    if (t == 0) {
        int run = 0;
        for (int b = 0; b < NUM_SCAN_BLOCKS; b++) {
            int v = sh[b];
            sh[b] = run;
            run += v;
        }
    }
    __syncthreads();
    if (t < NUM_SCAN_BLOCKS) g_bsum[t] = sh[t];
}

// ---------------- K4c: add offsets ----------------
__global__ void scan_add_kernel() {
    int i = blockIdx.x * blockDim.x + threadIdx.x;
    if (i < N_NODES) g_rowptr[i + 1] += g_bsum[i >> 10];
    if (i == 0) g_rowptr[0] = 0;
}

// ---------------- K5: scatter src ids into CSR order ----------------
__global__ void scatter_kernel(const int* __restrict__ ei) {
    int e = blockIdx.x * blockDim.x + threadIdx.x;
    if (e >= N_EDGES) return;
    int src = ei[e];
    int dst = ei[N_EDGES + e];
    int pos = g_rowptr[dst] + atomicAdd(&g_fill[dst], 1);
    g_src_sorted[pos] = src;
}

// ---------------- K6: warp-per-node softmax + message gather ----------------
// NOTE: max-shift dropped; differs from reference by eps*(e^max-1)/sum ~ 3e-8.
__global__ void msg_kernel(float* __restrict__ out, const float* __restrict__ bias) {
    int gtid = blockIdx.x * blockDim.x + threadIdx.x;
    int node = gtid >> 5;
    int lane = gtid & 31;
    if (node >= N_NODES) return;
    int p   = g_rowptr[node];
    int end = g_rowptr[node + 1];
    float el = g_el[node];
    float acc0 = 0.0f, acc1 = 0.0f, wsum = 0.0f;
    for (; p < end; p++) {
        int src = g_src_sorted[p];                 // broadcast
        float w = __expf(leaky(el + g_er[src]));   // broadcast
        wsum += w;
        const float* hp = g_h + (size_t)src * OUT_CH;
        acc0 = fmaf(w, hp[lane], acc0);
        acc1 = fmaf(w, hp[lane + 32], acc1);
    }
    float inv = 1.0f / (wsum + EPS_F);
    out[(size_t)node * OUT_CH + lane]      = acc0 * inv + bias[lane];
    out[(size_t)node * OUT_CH + 32 + lane] = acc1 * inv + bias[lane + 32];
}

// ---------------- launch ----------------
extern "C" void kernel_launch(void* const* d_in, const int* in_sizes, int n_in,
                              void* d_out, int out_size) {
    const float* x    = (const float*)d_in[0];
    const int*   ei   = (const int*)d_in[1];     // int32 (JAX x64 disabled)
    const float* W    = (const float*)d_in[2];
    const float* a_l  = (const float*)d_in[3];
    const float* a_r  = (const float*)d_in[4];
    const float* bias = (const float*)d_in[5];
    float* out = (float*)d_out;

    (void)in_sizes; (void)n_in; (void)out_size;

    init_kernel<<<(N_NODES + 255) / 256, 256>>>();
    gemm_kernel<<<(N_NODES + GEMM_ROWS - 1) / GEMM_ROWS, 128>>>(x, W);
    elr_kernel<<<(N_NODES * 32 + 255) / 256, 256>>>(a_l, a_r);
    hist_kernel<<<(N_EDGES + 255) / 256, 256>>>(ei);
    scan_block_kernel<<<NUM_SCAN_BLOCKS, SCAN_BS>>>();
    scan_bsum_kernel<<<1, 128>>>();
    scan_add_kernel<<<(N_NODES + 255) / 256, 256>>>();
    scatter_kernel<<<(N_EDGES + 255) / 256, 256>>>(ei);
    {
        long long threads = (long long)N_NODES * 32;
        int blocks = (int)((threads + 255) / 256);
        msg_kernel<<<blocks, 256>>>(out, bias);
    }
}